// round 2
// baseline (speedup 1.0000x reference)
#include <cuda_runtime.h>
#include <cstdint>

#define HH 512
#define WW 512
#define BB 2
#define PP 65536
#define CC 8
#define RR 4
#define HWPIX (HH * WW)
#define NPIX (BB * HWPIX)
#define NPTS (BB * PP)

#define ZNEAR 0.1f
#define ZFAR  10.0f
// GAMMA = 0.5 -> dividing by GAMMA == multiplying by 2 (exact)
#define INV_GAMMA 2.0f
#define EPS 1e-8f

// Scratch: per-pixel accumulator, 3 x float4 per pixel:
//   [0] = w*feat[0..3], [1] = w*feat[4..7], [2] = {sum_w, sum_w*z, sum_ws, pad}
__device__ float4 g_acc[NPIX * 3];
__device__ int    g_zmin[NPIX];

__device__ __forceinline__ void red_add_v4(float4* addr, float a, float b, float c, float d) {
    asm volatile("red.global.add.v4.f32 [%0], {%1, %2, %3, %4};"
                 :: "l"(addr), "f"(a), "f"(b), "f"(c), "f"(d)
                 : "memory");
}

// NDC coordinate of pixel center q, computed EXACTLY like the reference:
//   2.0 * q / (W-1) - 1.0   (IEEE divide, then subtract)
__device__ __forceinline__ float pix_ndc(int q) {
    return 2.0f * (float)q / 511.0f - 1.0f;
}

__global__ void init_kernel() {
    int i = blockIdx.x * blockDim.x + threadIdx.x;
    if (i >= NPIX) return;
    g_zmin[i] = __float_as_int(ZFAR);
    float4 z4 = make_float4(0.f, 0.f, 0.f, 0.f);
    g_acc[i * 3 + 0] = z4;
    g_acc[i * 3 + 1] = z4;
    g_acc[i * 3 + 2] = z4;
}

__global__ void zmin_kernel(const float* __restrict__ pts,
                            const float* __restrict__ max_radius) {
    __shared__ float s_ndc[512];
    for (int t = threadIdx.x; t < 512; t += blockDim.x)
        s_ndc[t] = pix_ndc(t);
    __syncthreads();

    int i = blockIdx.x * blockDim.x + threadIdx.x;
    if (i >= NPTS) return;
    float x = pts[i * 3 + 0];
    float y = pts[i * 3 + 1];
    float z = pts[i * 3 + 2];
    if (!(z > ZNEAR && z < ZFAR)) return;
    float mr = max_radius[0];
    float r2 = mr * mr;

    float px = (x + 1.0f) * 0.5f * (float)(WW - 1);
    float py = (y + 1.0f) * 0.5f * (float)(HH - 1);
    int cx = (int)rintf(px);
    int cy = (int)rintf(py);
    int zb = __float_as_int(z);
    int base = (i / PP) * HWPIX;

    for (int dy = -RR; dy <= RR; ++dy) {
        int qy = cy + dy;
        if ((unsigned)qy >= (unsigned)HH) continue;
        float ddy = s_ndc[qy] - y;
        float dy2 = ddy * ddy;
        int rowbase = base + qy * WW;
        #pragma unroll
        for (int dx = -RR; dx <= RR; ++dx) {
            int qx = cx + dx;
            if ((unsigned)qx >= (unsigned)WW) continue;
            float ddx = s_ndc[qx] - x;
            float d2 = ddx * ddx + dy2;
            if (d2 <= r2) {
                atomicMin(&g_zmin[rowbase + qx], zb);
            }
        }
    }
}

__global__ void splat_kernel(const float* __restrict__ pts,
                             const float* __restrict__ feats,
                             const float* __restrict__ sigmas,
                             const float* __restrict__ max_radius) {
    __shared__ float s_ndc[512];
    for (int t = threadIdx.x; t < 512; t += blockDim.x)
        s_ndc[t] = pix_ndc(t);
    __syncthreads();

    int i = blockIdx.x * blockDim.x + threadIdx.x;
    if (i >= NPTS) return;
    float x = pts[i * 3 + 0];
    float y = pts[i * 3 + 1];
    float z = pts[i * 3 + 2];
    if (!(z > ZNEAR && z < ZFAR)) return;
    float mr = max_radius[0];
    float r2 = mr * mr;

    float sg = sigmas[i];
    float inv2s2 = 0.5f / (sg * sg);   // per-point IEEE div; ~1e-7 rel vs ref's per-frag div

    const float4* fp = reinterpret_cast<const float4*>(feats + (size_t)i * CC);
    float4 f0 = fp[0];
    float4 f1 = fp[1];

    float px = (x + 1.0f) * 0.5f * (float)(WW - 1);
    float py = (y + 1.0f) * 0.5f * (float)(HH - 1);
    int cx = (int)rintf(px);
    int cy = (int)rintf(py);
    int base = (i / PP) * HWPIX;

    for (int dy = -RR; dy <= RR; ++dy) {
        int qy = cy + dy;
        if ((unsigned)qy >= (unsigned)HH) continue;
        float ddy = s_ndc[qy] - y;
        float dy2 = ddy * ddy;
        int rowbase = base + qy * WW;
        #pragma unroll
        for (int dx = -RR; dx <= RR; ++dx) {
            int qx = cx + dx;
            if ((unsigned)qx >= (unsigned)WW) continue;
            float ddx = s_ndc[qx] - x;
            float d2 = ddx * ddx + dy2;
            if (d2 <= r2) {
                int pid = rowbase + qx;
                float zm = __int_as_float(g_zmin[pid]);
                float ws = __expf(-d2 * inv2s2);
                float w = ws * __expf(-(z - zm) * INV_GAMMA);
                float4* ap = &g_acc[pid * 3];
                red_add_v4(ap + 0, w * f0.x, w * f0.y, w * f0.z, w * f0.w);
                red_add_v4(ap + 1, w * f1.x, w * f1.y, w * f1.z, w * f1.w);
                red_add_v4(ap + 2, w, w * z, ws, 0.0f);
            }
        }
    }
}

__global__ void finalize_kernel(float* __restrict__ out) {
    int i = blockIdx.x * blockDim.x + threadIdx.x;
    if (i >= NPIX) return;
    float4 a0 = g_acc[i * 3 + 0];
    float4 a1 = g_acc[i * 3 + 1];
    float4 a2 = g_acc[i * 3 + 2];
    float denom = a2.x + EPS;
    float inv = 1.0f / denom;

    float4 c0 = make_float4(a0.x * inv, a0.y * inv, a0.z * inv, a0.w * inv);
    float4 c1 = make_float4(a1.x * inv, a1.y * inv, a1.z * inv, a1.w * inv);
    float4* outc = reinterpret_cast<float4*>(out);
    outc[i * 2 + 0] = c0;
    outc[i * 2 + 1] = c1;

    out[(size_t)NPIX * CC + i] = a2.y * inv;                    // depth
    out[(size_t)NPIX * CC + NPIX + i] = 1.0f - __expf(-a2.z);   // mask
}

extern "C" void kernel_launch(void* const* d_in, const int* in_sizes, int n_in,
                              void* d_out, int out_size) {
    const float* pts        = (const float*)d_in[0];  // [B,P,3]
    const float* feats      = (const float*)d_in[1];  // [B,P,8]
    const float* sigmas     = (const float*)d_in[2];  // [B,P]
    const float* max_radius = (const float*)d_in[3];  // scalar
    float* out = (float*)d_out;

    {
        int threads = 256;
        int blocks = (NPIX + threads - 1) / threads;
        init_kernel<<<blocks, threads>>>();
    }
    {
        int threads = 256;
        int blocks = (NPTS + threads - 1) / threads;
        zmin_kernel<<<blocks, threads>>>(pts, max_radius);
        splat_kernel<<<blocks, threads>>>(pts, feats, sigmas, max_radius);
    }
    {
        int threads = 256;
        int blocks = (NPIX + threads - 1) / threads;
        finalize_kernel<<<blocks, threads>>>(out);
    }
}